// round 8
// baseline (speedup 1.0000x reference)
#include <cuda_runtime.h>
#include <math.h>

#define H      128
#define H3     384
#define HALF   64
#define BATCH  64
#define TT     2048
#define TILE   128   // time steps staged per smem chunk

typedef unsigned long long ull_t;

// feat[b*256 + dir*128 + i] = mean over t of hidden state
__device__ float g_feat[BATCH * 2 * H];

__device__ __forceinline__ ull_t pack2(float lo, float hi) {
    return (ull_t)__float_as_uint(lo) | ((ull_t)__float_as_uint(hi) << 32);
}
__device__ __forceinline__ float lo2(ull_t v) { return __uint_as_float((unsigned)v); }
__device__ __forceinline__ float hi2(ull_t v) { return __uint_as_float((unsigned)(v >> 32)); }

__device__ __forceinline__ ull_t ffma2(ull_t a, ull_t b, ull_t c) {
    ull_t d;
    asm("fma.rn.f32x2 %0, %1, %2, %3;" : "=l"(d) : "l"(a), "l"(b), "l"(c));
    return d;
}
__device__ __forceinline__ float ex2f(float x) {
    float r; asm("ex2.approx.ftz.f32 %0, %1;" : "=f"(r) : "f"(x)); return r;
}
__device__ __forceinline__ float rcpf(float x) {
    float r; asm("rcp.approx.ftz.f32 %0, %1;" : "=f"(r) : "f"(x)); return r;
}

#define L2E 1.4426950408889634f

__device__ __forceinline__ float fsig(float x) {
    return rcpf(1.0f + ex2f(-L2E * x));
}
__device__ __forceinline__ float ftanh(float x) {
    return 2.0f * rcpf(1.0f + ex2f(-2.0f * L2E * x)) - 1.0f;
}

// dummy kernel so ncu (-s 5 -c 1) lands on the GRU kernel
__global__ void nop_kernel() {}

// One persistent block per (batch, direction). 256 threads.
// Thread t: unit i = t>>1, k-half = t&1 — the two k-halves of a unit sit in
// ADJACENT LANES, so the partial-dot combine is shfl_xor(1), not smem.
// Each thread: all three gate partial-dots over its 64-element k-half
// (FFMA2 streams share the h operand -> RF operand-reuse, proven in R7).
// Even lane: gate math + h update (ping-pong h). Odd lane: next-step xw.
// ONE __syncthreads per step.
__global__ void __launch_bounds__(256, 1) gru_persist_kernel(
    const float* __restrict__ y, const float* __restrict__ u,
    const float* __restrict__ Wi_f, const float* __restrict__ bi_f,
    const float* __restrict__ Wh_f, const float* __restrict__ bhn_f,
    const float* __restrict__ Wi_b, const float* __restrict__ bi_b,
    const float* __restrict__ Wh_b, const float* __restrict__ bhn_b)
{
    const int blk  = blockIdx.x;        // 0..127
    const int b    = blk & (BATCH - 1);
    const int dir  = blk >> 6;          // 0 = fwd, 1 = bwd
    const int t    = threadIdx.x;       // 0..255
    const int i    = t >> 1;            // unit 0..127
    const int half = t & 1;             // k-half
    const int k0   = half * HALF;
    const bool ev  = (half == 0);

    const float* Wi  = dir ? Wi_b  : Wi_f;
    const float* bi  = dir ? bi_b  : bi_f;
    const float* Wh  = dir ? Wh_b  : Wh_f;
    const float* bhn = dir ? bhn_b : bhn_f;

    // ---- register-resident recurrent weights: 3 gates x half-k, packed ----
    ull_t wr[HALF / 2], wz[HALF / 2], wn[HALF / 2];
#pragma unroll
    for (int m = 0; m < HALF / 2; ++m) {
        const float* r0 = Wh + (size_t)(k0 + 2 * m)     * H3;
        const float* r1 = Wh + (size_t)(k0 + 2 * m + 1) * H3;
        wr[m] = pack2(r0[i],         r1[i]);
        wz[m] = pack2(r0[i + H],     r1[i + H]);
        wn[m] = pack2(r0[i + 2 * H], r1[i + 2 * H]);
    }

    // ---- shared state ----
    __shared__ __align__(16) float  h_s[2][H];        // ping-pong hidden
    __shared__ __align__(16) float4 yu_s[TILE * 2];   // per step: y(4)+u(4)
    __shared__ __align__(16) float4 wi4_s[2 * H3];    // Wi columns, 2 float4

    for (int col = t; col < H3; col += 256) {
        wi4_s[col]      = make_float4(Wi[0 * H3 + col], Wi[1 * H3 + col],
                                      Wi[2 * H3 + col], Wi[3 * H3 + col]);
        wi4_s[H3 + col] = make_float4(Wi[4 * H3 + col], Wi[5 * H3 + col],
                                      Wi[6 * H3 + col], Wi[7 * H3 + col]);
    }

    // role scalars: even lane needs bhn; odd lane needs the 3 biases
    float bhn_i = 0.0f, bir = 0.0f, biz = 0.0f, bin = 0.0f;
    if (ev) bhn_i = bhn[i];
    else { bir = bi[i]; biz = bi[i + H]; bin = bi[i + 2 * H]; }

    if (t < H) { h_s[0][t] = 0.0f; }
    __syncthreads();

    float hsum = 0.0f;                  // even lanes only
    int p = 0;
    float xwr = 0.0f, xwz = 0.0f, xwn = 0.0f;   // odd lanes: xw of step s

    const int nchunk = TT / TILE;
    for (int c = 0; c < nchunk; ++c) {
        const int t0 = dir ? (TT - (c + 1) * TILE) : (c * TILE);

        // stage chunk inputs: thread t loads yu_s[t] (t = 2*step + sel)
        {
            const int st  = t >> 1;
            const float* src = half ? u : y;
            yu_s[t] = *(const float4*)(src + ((size_t)b * TT + t0 + st) * 4);
        }
        __syncthreads();

        const int tt0 = dir ? (TILE - 1) : 0;
        const int sgn = dir ? -1 : 1;

        // prologue: odd lanes compute xw for step 0
        if (!ev) {
            const float4 ya = yu_s[2 * tt0];
            const float4 ub = yu_s[2 * tt0 + 1];
            const float4 war = wi4_s[i],         wbr = wi4_s[H3 + i];
            const float4 waz = wi4_s[i + H],     wbz = wi4_s[H3 + i + H];
            const float4 wan = wi4_s[i + 2 * H], wbn = wi4_s[H3 + i + 2 * H];
            float xr = bir, xz = biz, xn = bin;
            xr = fmaf(ya.x, war.x, xr); xr = fmaf(ya.y, war.y, xr);
            xr = fmaf(ya.z, war.z, xr); xr = fmaf(ya.w, war.w, xr);
            xr = fmaf(ub.x, wbr.x, xr); xr = fmaf(ub.y, wbr.y, xr);
            xr = fmaf(ub.z, wbr.z, xr); xr = fmaf(ub.w, wbr.w, xr);
            xz = fmaf(ya.x, waz.x, xz); xz = fmaf(ya.y, waz.y, xz);
            xz = fmaf(ya.z, waz.z, xz); xz = fmaf(ya.w, waz.w, xz);
            xz = fmaf(ub.x, wbz.x, xz); xz = fmaf(ub.y, wbz.y, xz);
            xz = fmaf(ub.z, wbz.z, xz); xz = fmaf(ub.w, wbz.w, xz);
            xn = fmaf(ya.x, wan.x, xn); xn = fmaf(ya.y, wan.y, xn);
            xn = fmaf(ya.z, wan.z, xn); xn = fmaf(ya.w, wan.w, xn);
            xn = fmaf(ub.x, wbn.x, xn); xn = fmaf(ub.y, wbn.y, xn);
            xn = fmaf(ub.z, wbn.z, xn); xn = fmaf(ub.w, wbn.w, xn);
            xwr = xr; xwz = xz; xwn = xn;
        }

        for (int s = 0; s < TILE; ++s) {
            // ---- 3 partial dots over h[p][k0:k0+64] (all threads) ----
            const ulonglong2* h2 = (const ulonglong2*)(h_s[p] + k0);
            ull_t ar = 0ull, az = 0ull, an = 0ull;
#pragma unroll
            for (int m = 0; m < HALF / 4; ++m) {
                const ulonglong2 hv = h2[m];   // broadcast; shared 3 ways
                ar = ffma2(hv.x, wr[2 * m],     ar);
                az = ffma2(hv.x, wz[2 * m],     az);
                an = ffma2(hv.x, wn[2 * m],     an);
                ar = ffma2(hv.y, wr[2 * m + 1], ar);
                az = ffma2(hv.y, wz[2 * m + 1], az);
                an = ffma2(hv.y, wn[2 * m + 1], an);
            }
            const float hold = h_s[p][i];              // early issue
            const float pr = lo2(ar) + hi2(ar);
            const float pz = lo2(az) + hi2(az);
            const float pn = lo2(an) + hi2(an);

            // pair exchange: partner's partials + xw (all lanes participate)
            const unsigned FULL = 0xFFFFFFFFu;
            const float opr = __shfl_xor_sync(FULL, pr,  1);
            const float opz = __shfl_xor_sync(FULL, pz,  1);
            const float opn = __shfl_xor_sync(FULL, pn,  1);
            const float oxr = __shfl_xor_sync(FULL, xwr, 1);
            const float oxz = __shfl_xor_sync(FULL, xwz, 1);
            const float oxn = __shfl_xor_sync(FULL, xwn, 1);

            if (ev) {
                // ---- gate math + h update (even lanes) ----
                const float r = fsig(oxr + (pr + opr));
                const float z = fsig(oxz + (pz + opz));
                const float nfull = (pn + opn) + bhn_i;
                const float arg = fmaf(r, nfull, oxn);
                const float q   = ex2f(-2.0f * L2E * arg);
                const float rc  = rcpf(1.0f + q);
                const float hn  = fmaf(rc, 2.0f - 2.0f * z,
                                       fmaf(z, hold + 1.0f, -1.0f));
                hsum += hn;
                h_s[p ^ 1][i] = hn;
            } else if (s + 1 < TILE) {
                // ---- odd lanes: xw for next step (off critical path) ----
                const int tt_n = tt0 + sgn * (s + 1);
                const float4 ya = yu_s[2 * tt_n];
                const float4 ub = yu_s[2 * tt_n + 1];
                const float4 war = wi4_s[i],         wbr = wi4_s[H3 + i];
                const float4 waz = wi4_s[i + H],     wbz = wi4_s[H3 + i + H];
                const float4 wan = wi4_s[i + 2 * H], wbn = wi4_s[H3 + i + 2 * H];
                float xr = bir, xz = biz, xn = bin;
                xr = fmaf(ya.x, war.x, xr); xr = fmaf(ya.y, war.y, xr);
                xr = fmaf(ya.z, war.z, xr); xr = fmaf(ya.w, war.w, xr);
                xr = fmaf(ub.x, wbr.x, xr); xr = fmaf(ub.y, wbr.y, xr);
                xr = fmaf(ub.z, wbr.z, xr); xr = fmaf(ub.w, wbr.w, xr);
                xz = fmaf(ya.x, waz.x, xz); xz = fmaf(ya.y, waz.y, xz);
                xz = fmaf(ya.z, waz.z, xz); xz = fmaf(ya.w, waz.w, xz);
                xz = fmaf(ub.x, wbz.x, xz); xz = fmaf(ub.y, wbz.y, xz);
                xz = fmaf(ub.z, wbz.z, xz); xz = fmaf(ub.w, wbz.w, xz);
                xn = fmaf(ya.x, wan.x, xn); xn = fmaf(ya.y, wan.y, xn);
                xn = fmaf(ya.z, wan.z, xn); xn = fmaf(ya.w, wan.w, xn);
                xn = fmaf(ub.x, wbn.x, xn); xn = fmaf(ub.y, wbn.y, xn);
                xn = fmaf(ub.z, wbn.z, xn); xn = fmaf(ub.w, wbn.w, xn);
                xwr = xr; xwz = xz; xwn = xn;
            }

            __syncthreads();              // h[p^1] visible; ONE bar per step
            p ^= 1;
        }
    }

    if (ev)
        g_feat[b * (2 * H) + dir * H + i] = hsum * (1.0f / (float)TT);
}

// MLP heads: 256 -> 128 -> 64 -> 20, tanh, tanh, linear.
__global__ void __launch_bounds__(128) mlp_kernel(
    const float* __restrict__ mW0, const float* __restrict__ mb0,
    const float* __restrict__ mW1, const float* __restrict__ mb1,
    const float* __restrict__ mW2, const float* __restrict__ mb2,
    const float* __restrict__ sW0, const float* __restrict__ sb0,
    const float* __restrict__ sW1, const float* __restrict__ sb1,
    const float* __restrict__ sW2, const float* __restrict__ sb2,
    float* __restrict__ out)
{
    const int b    = blockIdx.x & (BATCH - 1);
    const int head = blockIdx.x >> 6;
    const int j    = threadIdx.x;

    const float* W0 = head ? sW0 : mW0;
    const float* b0 = head ? sb0 : mb0;
    const float* W1 = head ? sW1 : mW1;
    const float* b1 = head ? sb1 : mb1;
    const float* W2 = head ? sW2 : mW2;
    const float* b2 = head ? sb2 : mb2;

    __shared__ float feat_s[256];
    __shared__ float h1_s[128];
    __shared__ float h2_s[64];

    feat_s[j]       = g_feat[b * 256 + j];
    feat_s[j + 128] = g_feat[b * 256 + j + 128];
    __syncthreads();

    {   // layer 0: 256 -> 128
        float acc = b0[j];
#pragma unroll 8
        for (int i = 0; i < 256; ++i)
            acc = fmaf(feat_s[i], __ldg(W0 + (size_t)i * 128 + j), acc);
        h1_s[j] = ftanh(acc);
    }
    __syncthreads();

    if (j < 64) {   // layer 1: 128 -> 64
        float acc = b1[j];
#pragma unroll 8
        for (int i = 0; i < 128; ++i)
            acc = fmaf(h1_s[i], __ldg(W1 + (size_t)i * 64 + j), acc);
        h2_s[j] = ftanh(acc);
    }
    __syncthreads();

    if (j < 20) {   // layer 2: 64 -> 20
        float acc = b2[j];
#pragma unroll
        for (int i = 0; i < 64; ++i)
            acc = fmaf(h2_s[i], __ldg(W2 + (size_t)i * 20 + j), acc);
        out[head * (BATCH * 20) + b * 20 + j] = acc;
    }
}

extern "C" void kernel_launch(void* const* d_in, const int* in_sizes, int n_in,
                              void* d_out, int out_size)
{
    const float* y     = (const float*)d_in[0];
    const float* u     = (const float*)d_in[1];
    const float* Wi_f  = (const float*)d_in[2];
    const float* bi_f  = (const float*)d_in[3];
    const float* Wh_f  = (const float*)d_in[4];
    const float* bhn_f = (const float*)d_in[5];
    const float* Wi_b  = (const float*)d_in[6];
    const float* bi_b  = (const float*)d_in[7];
    const float* Wh_b  = (const float*)d_in[8];
    const float* bhn_b = (const float*)d_in[9];
    const float* mW0   = (const float*)d_in[10];
    const float* mb0   = (const float*)d_in[11];
    const float* mW1   = (const float*)d_in[12];
    const float* mb1   = (const float*)d_in[13];
    const float* mW2   = (const float*)d_in[14];
    const float* mb2   = (const float*)d_in[15];
    const float* sW0   = (const float*)d_in[16];
    const float* sb0   = (const float*)d_in[17];
    const float* sW1   = (const float*)d_in[18];
    const float* sb1   = (const float*)d_in[19];
    const float* sW2   = (const float*)d_in[20];
    const float* sb2   = (const float*)d_in[21];

    nop_kernel<<<1, 32>>>();
    gru_persist_kernel<<<BATCH * 2, 256>>>(y, u, Wi_f, bi_f, Wh_f, bhn_f,
                                           Wi_b, bi_b, Wh_b, bhn_b);
    nop_kernel<<<1, 32>>>();
    mlp_kernel<<<BATCH * 2, 128>>>(mW0, mb0, mW1, mb1, mW2, mb2,
                                   sW0, sb0, sW1, sb1, sW2, sb2,
                                   (float*)d_out);
}

// round 9
// speedup vs baseline: 1.1673x; 1.1673x over previous
#include <cuda_runtime.h>
#include <math.h>

#define H      128
#define H3     384
#define HALF   64
#define BATCH  64
#define TT     2048
#define TILE   128   // time steps staged per smem chunk

typedef unsigned long long ull_t;

// feat[b*256 + dir*128 + i] = mean over t of hidden state
__device__ float g_feat[BATCH * 2 * H];

__device__ __forceinline__ ull_t pack2(float lo, float hi) {
    return (ull_t)__float_as_uint(lo) | ((ull_t)__float_as_uint(hi) << 32);
}
__device__ __forceinline__ float lo2(ull_t v) { return __uint_as_float((unsigned)v); }
__device__ __forceinline__ float hi2(ull_t v) { return __uint_as_float((unsigned)(v >> 32)); }

__device__ __forceinline__ ull_t ffma2(ull_t a, ull_t b, ull_t c) {
    ull_t d;
    asm("fma.rn.f32x2 %0, %1, %2, %3;" : "=l"(d) : "l"(a), "l"(b), "l"(c));
    return d;
}
__device__ __forceinline__ float ex2f(float x) {
    float r; asm("ex2.approx.ftz.f32 %0, %1;" : "=f"(r) : "f"(x)); return r;
}
__device__ __forceinline__ float rcpf(float x) {
    float r; asm("rcp.approx.ftz.f32 %0, %1;" : "=f"(r) : "f"(x)); return r;
}
__device__ __forceinline__ float tanhf_hw(float x) {
    float r; asm("tanh.approx.f32 %0, %1;" : "=f"(r) : "f"(x)); return r;
}

#define L2E 1.4426950408889634f

// gate sigmoid via HW tanh: sig(x) = 0.5*tanh(0.5x) + 0.5  (abs err ~5e-4)
__device__ __forceinline__ float fsig_hw(float x) {
    return fmaf(0.5f, tanhf_hw(0.5f * x), 0.5f);
}
__device__ __forceinline__ float ftanh(float x) {   // accurate path (MLP / n)
    return 2.0f * rcpf(1.0f + ex2f(-2.0f * L2E * x)) - 1.0f;
}

// dummy kernel so ncu (-s 5 -c 1) lands on the GRU kernel
__global__ void nop_kernel() {}

// One persistent block per (batch, direction). 256 threads. (R7 layout)
// Thread t: unit i = t & 127, k-half = t >> 7.
//   half 0 (warps 0-3): updaters — combine partials, gates, h update.
//   half 1 (warps 4-7): write partials; bar.arrive; then next-step xw
//                       (overlapping the updaters' phase 2).
__global__ void __launch_bounds__(256, 1) gru_persist_kernel(
    const float* __restrict__ y, const float* __restrict__ u,
    const float* __restrict__ Wi_f, const float* __restrict__ bi_f,
    const float* __restrict__ Wh_f, const float* __restrict__ bhn_f,
    const float* __restrict__ Wi_b, const float* __restrict__ bi_b,
    const float* __restrict__ Wh_b, const float* __restrict__ bhn_b)
{
    const int blk  = blockIdx.x;        // 0..127
    const int b    = blk & (BATCH - 1);
    const int dir  = blk >> 6;          // 0 = fwd, 1 = bwd
    const int t    = threadIdx.x;       // 0..255
    const int i    = t & (H - 1);       // unit 0..127
    const int half = t >> 7;            // k-half
    const int k0   = half * HALF;
    const bool upd = (t < H);           // warps 0-3

    const float* Wi  = dir ? Wi_b  : Wi_f;
    const float* bi  = dir ? bi_b  : bi_f;
    const float* Wh  = dir ? Wh_b  : Wh_f;
    const float* bhn = dir ? bhn_b : bhn_f;

    // ---- register-resident recurrent weights: 3 gates x half-k, packed ----
    ull_t wr[HALF / 2], wz[HALF / 2], wn[HALF / 2];
#pragma unroll
    for (int m = 0; m < HALF / 2; ++m) {
        const float* r0 = Wh + (size_t)(k0 + 2 * m)     * H3;
        const float* r1 = Wh + (size_t)(k0 + 2 * m + 1) * H3;
        wr[m] = pack2(r0[i],         r1[i]);
        wz[m] = pack2(r0[i + H],     r1[i + H]);
        wn[m] = pack2(r0[i + 2 * H], r1[i + 2 * H]);
    }

    // ---- shared state ----
    __shared__ __align__(16) float  h_s[H];
    __shared__ __align__(16) float4 part_s[H];        // (pr,pz,pn,-) from half 1
    __shared__ __align__(16) float4 xw_s[2][H];       // ping-pong (xwr,xwz,xwn,-)
    __shared__ __align__(16) float4 yu_s[TILE * 2];   // per step: y(4)+u(4)
    __shared__ __align__(16) float4 wi4_s[2 * H3];    // Wi columns, 2 float4 each

    for (int col = t; col < H3; col += 256) {
        wi4_s[col]      = make_float4(Wi[0 * H3 + col], Wi[1 * H3 + col],
                                      Wi[2 * H3 + col], Wi[3 * H3 + col]);
        wi4_s[H3 + col] = make_float4(Wi[4 * H3 + col], Wi[5 * H3 + col],
                                      Wi[6 * H3 + col], Wi[7 * H3 + col]);
    }

    float bhn_i = 0.0f, bir = 0.0f, biz = 0.0f, bin = 0.0f;
    if (upd) {
        bhn_i = bhn[i];
    } else {
        bir = bi[i]; biz = bi[i + H]; bin = bi[i + 2 * H];
    }

    if (t < H) h_s[t] = 0.0f;
    __syncthreads();

    float hsum = 0.0f;                  // updaters only

    const int nchunk = TT / TILE;
    for (int c = 0; c < nchunk; ++c) {
        const int t0 = dir ? (TT - (c + 1) * TILE) : (c * TILE);

        if (!upd) {                     // half-1 threads stage inputs
            const int tc = t0 + i;
            yu_s[2 * i]     = *(const float4*)(y + ((size_t)b * TT + tc) * 4);
            yu_s[2 * i + 1] = *(const float4*)(u + ((size_t)b * TT + tc) * 4);
        }
        __syncthreads();

        const int tt0 = dir ? (TILE - 1) : 0;
        const int sgn = dir ? -1 : 1;

        // chunk prologue: xw for step 0 into xw_s[0] (half-1 threads)
        if (!upd) {
            const float4 ya = yu_s[2 * tt0];
            const float4 ub = yu_s[2 * tt0 + 1];
            const float4 war = wi4_s[i],          wbr = wi4_s[H3 + i];
            const float4 waz = wi4_s[i + H],      wbz = wi4_s[H3 + i + H];
            const float4 wan = wi4_s[i + 2 * H],  wbn = wi4_s[H3 + i + 2 * H];
            float xr = bir, xz = biz, xn = bin;
            xr = fmaf(ya.x, war.x, xr); xr = fmaf(ya.y, war.y, xr);
            xr = fmaf(ya.z, war.z, xr); xr = fmaf(ya.w, war.w, xr);
            xr = fmaf(ub.x, wbr.x, xr); xr = fmaf(ub.y, wbr.y, xr);
            xr = fmaf(ub.z, wbr.z, xr); xr = fmaf(ub.w, wbr.w, xr);
            xz = fmaf(ya.x, waz.x, xz); xz = fmaf(ya.y, waz.y, xz);
            xz = fmaf(ya.z, waz.z, xz); xz = fmaf(ya.w, waz.w, xz);
            xz = fmaf(ub.x, wbz.x, xz); xz = fmaf(ub.y, wbz.y, xz);
            xz = fmaf(ub.z, wbz.z, xz); xz = fmaf(ub.w, wbz.w, xz);
            xn = fmaf(ya.x, wan.x, xn); xn = fmaf(ya.y, wan.y, xn);
            xn = fmaf(ya.z, wan.z, xn); xn = fmaf(ya.w, wan.w, xn);
            xn = fmaf(ub.x, wbn.x, xn); xn = fmaf(ub.y, wbn.y, xn);
            xn = fmaf(ub.z, wbn.z, xn); xn = fmaf(ub.w, wbn.w, xn);
            xw_s[0][i] = make_float4(xr, xz, xn, 0.0f);
        }

        for (int s = 0; s < TILE; ++s) {
            // ---- phase 1: 3 partial dots over h[k0:k0+64] (all threads) ----
            const ulonglong2* h2 = (const ulonglong2*)(h_s + k0);
            ull_t ar = 0ull, az = 0ull, an = 0ull;
#pragma unroll
            for (int m = 0; m < HALF / 4; ++m) {
                const ulonglong2 hv = h2[m];   // broadcast; shared 3 ways
                ar = ffma2(hv.x, wr[2 * m],     ar);
                az = ffma2(hv.x, wz[2 * m],     az);
                an = ffma2(hv.x, wn[2 * m],     an);
                ar = ffma2(hv.y, wr[2 * m + 1], ar);
                az = ffma2(hv.y, wz[2 * m + 1], az);
                an = ffma2(hv.y, wn[2 * m + 1], an);
            }
            const float pr = lo2(ar) + hi2(ar);
            const float pz = lo2(az) + hi2(az);
            const float pn = lo2(an) + hi2(an);

            if (upd) {
                const float hold = h_s[i];               // pre-bar issue
                asm volatile("bar.sync 1, 256;");        // wait: part_s ready
                // ---- phase 2: combine + gates + h update ----
                const float4 p   = part_s[i];
                const float4 xwv = xw_s[s & 1][i];
                const float r = fsig_hw((xwv.x + pr) + p.x);   // HW tanh gate
                const float z = fsig_hw((xwv.y + pz) + p.y);   // HW tanh gate
                const float pn_full = (pn + p.z) + bhn_i;
                const float arg = fmaf(r, pn_full, xwv.z);
                const float q   = ex2f(-2.0f * L2E * arg);     // accurate n
                const float rc  = rcpf(1.0f + q);
                const float hn  = fmaf(rc, 2.0f - 2.0f * z,
                                       fmaf(z, hold + 1.0f, -1.0f));
                hsum += hn;
                h_s[i] = hn;
            } else {
                part_s[i] = make_float4(pr, pz, pn, 0.0f);
                asm volatile("bar.arrive 1, 256;");      // release, no block
                // next step's xw AFTER the arrive: overlaps updaters' phase 2
                if (s + 1 < TILE) {
                    const int tt_n = tt0 + sgn * (s + 1);
                    const float4 ya = yu_s[2 * tt_n];
                    const float4 ub = yu_s[2 * tt_n + 1];
                    const float4 war = wi4_s[i],         wbr = wi4_s[H3 + i];
                    const float4 waz = wi4_s[i + H],     wbz = wi4_s[H3 + i + H];
                    const float4 wan = wi4_s[i + 2 * H], wbn = wi4_s[H3 + i + 2 * H];
                    float xr = bir, xz = biz, xn = bin;
                    xr = fmaf(ya.x, war.x, xr); xr = fmaf(ya.y, war.y, xr);
                    xr = fmaf(ya.z, war.z, xr); xr = fmaf(ya.w, war.w, xr);
                    xr = fmaf(ub.x, wbr.x, xr); xr = fmaf(ub.y, wbr.y, xr);
                    xr = fmaf(ub.z, wbr.z, xr); xr = fmaf(ub.w, wbr.w, xr);
                    xz = fmaf(ya.x, waz.x, xz); xz = fmaf(ya.y, waz.y, xz);
                    xz = fmaf(ya.z, waz.z, xz); xz = fmaf(ya.w, waz.w, xz);
                    xz = fmaf(ub.x, wbz.x, xz); xz = fmaf(ub.y, wbz.y, xz);
                    xz = fmaf(ub.z, wbz.z, xz); xz = fmaf(ub.w, wbz.w, xz);
                    xn = fmaf(ya.x, wan.x, xn); xn = fmaf(ya.y, wan.y, xn);
                    xn = fmaf(ya.z, wan.z, xn); xn = fmaf(ya.w, wan.w, xn);
                    xn = fmaf(ub.x, wbn.x, xn); xn = fmaf(ub.y, wbn.y, xn);
                    xn = fmaf(ub.z, wbn.z, xn); xn = fmaf(ub.w, wbn.w, xn);
                    xw_s[(s + 1) & 1][i] = make_float4(xr, xz, xn, 0.0f);
                }
            }
            __syncthreads();                             // bar2: h ready
        }
    }

    if (upd)
        g_feat[b * (2 * H) + dir * H + i] = hsum * (1.0f / (float)TT);
}

// MLP heads: 256 -> 128 -> 64 -> 20, tanh, tanh, linear. (accurate tanh path)
__global__ void __launch_bounds__(128) mlp_kernel(
    const float* __restrict__ mW0, const float* __restrict__ mb0,
    const float* __restrict__ mW1, const float* __restrict__ mb1,
    const float* __restrict__ mW2, const float* __restrict__ mb2,
    const float* __restrict__ sW0, const float* __restrict__ sb0,
    const float* __restrict__ sW1, const float* __restrict__ sb1,
    const float* __restrict__ sW2, const float* __restrict__ sb2,
    float* __restrict__ out)
{
    const int b    = blockIdx.x & (BATCH - 1);
    const int head = blockIdx.x >> 6;
    const int j    = threadIdx.x;

    const float* W0 = head ? sW0 : mW0;
    const float* b0 = head ? sb0 : mb0;
    const float* W1 = head ? sW1 : mW1;
    const float* b1 = head ? sb1 : mb1;
    const float* W2 = head ? sW2 : mW2;
    const float* b2 = head ? sb2 : mb2;

    __shared__ float feat_s[256];
    __shared__ float h1_s[128];
    __shared__ float h2_s[64];

    feat_s[j]       = g_feat[b * 256 + j];
    feat_s[j + 128] = g_feat[b * 256 + j + 128];
    __syncthreads();

    {   // layer 0: 256 -> 128
        float acc = b0[j];
#pragma unroll 8
        for (int i = 0; i < 256; ++i)
            acc = fmaf(feat_s[i], __ldg(W0 + (size_t)i * 128 + j), acc);
        h1_s[j] = ftanh(acc);
    }
    __syncthreads();

    if (j < 64) {   // layer 1: 128 -> 64
        float acc = b1[j];
#pragma unroll 8
        for (int i = 0; i < 128; ++i)
            acc = fmaf(h1_s[i], __ldg(W1 + (size_t)i * 64 + j), acc);
        h2_s[j] = ftanh(acc);
    }
    __syncthreads();

    if (j < 20) {   // layer 2: 64 -> 20
        float acc = b2[j];
#pragma unroll
        for (int i = 0; i < 64; ++i)
            acc = fmaf(h2_s[i], __ldg(W2 + (size_t)i * 20 + j), acc);
        out[head * (BATCH * 20) + b * 20 + j] = acc;
    }
}

extern "C" void kernel_launch(void* const* d_in, const int* in_sizes, int n_in,
                              void* d_out, int out_size)
{
    const float* y     = (const float*)d_in[0];
    const float* u     = (const float*)d_in[1];
    const float* Wi_f  = (const float*)d_in[2];
    const float* bi_f  = (const float*)d_in[3];
    const float* Wh_f  = (const float*)d_in[4];
    const float* bhn_f = (const float*)d_in[5];
    const float* Wi_b  = (const float*)d_in[6];
    const float* bi_b  = (const float*)d_in[7];
    const float* Wh_b  = (const float*)d_in[8];
    const float* bhn_b = (const float*)d_in[9];
    const float* mW0   = (const float*)d_in[10];
    const float* mb0   = (const float*)d_in[11];
    const float* mW1   = (const float*)d_in[12];
    const float* mb1   = (const float*)d_in[13];
    const float* mW2   = (const float*)d_in[14];
    const float* mb2   = (const float*)d_in[15];
    const float* sW0   = (const float*)d_in[16];
    const float* sb0   = (const float*)d_in[17];
    const float* sW1   = (const float*)d_in[18];
    const float* sb1   = (const float*)d_in[19];
    const float* sW2   = (const float*)d_in[20];
    const float* sb2   = (const float*)d_in[21];

    nop_kernel<<<1, 32>>>();
    gru_persist_kernel<<<BATCH * 2, 256>>>(y, u, Wi_f, bi_f, Wh_f, bhn_f,
                                           Wi_b, bi_b, Wh_b, bhn_b);
    nop_kernel<<<1, 32>>>();
    mlp_kernel<<<BATCH * 2, 128>>>(mW0, mb0, mW1, mb1, mW2, mb2,
                                   sW0, sb0, sW1, sb1, sW2, sb2,
                                   (float*)d_out);
}

// round 10
// speedup vs baseline: 1.2012x; 1.0291x over previous
#include <cuda_runtime.h>
#include <math.h>

#define H      128
#define H3     384
#define HALF   64
#define BATCH  64
#define TT     2048
#define TILE   128   // time steps staged per smem chunk

typedef unsigned long long ull_t;

// feat[b*256 + dir*128 + i] = mean over t of hidden state
__device__ float g_feat[BATCH * 2 * H];

__device__ __forceinline__ ull_t pack2(float lo, float hi) {
    return (ull_t)__float_as_uint(lo) | ((ull_t)__float_as_uint(hi) << 32);
}
__device__ __forceinline__ float lo2(ull_t v) { return __uint_as_float((unsigned)v); }
__device__ __forceinline__ float hi2(ull_t v) { return __uint_as_float((unsigned)(v >> 32)); }

__device__ __forceinline__ ull_t ffma2(ull_t a, ull_t b, ull_t c) {
    ull_t d;
    asm("fma.rn.f32x2 %0, %1, %2, %3;" : "=l"(d) : "l"(a), "l"(b), "l"(c));
    return d;
}
__device__ __forceinline__ float ex2f(float x) {
    float r; asm("ex2.approx.ftz.f32 %0, %1;" : "=f"(r) : "f"(x)); return r;
}
__device__ __forceinline__ float rcpf(float x) {
    float r; asm("rcp.approx.ftz.f32 %0, %1;" : "=f"(r) : "f"(x)); return r;
}
__device__ __forceinline__ float tanhf_hw(float x) {
    float r; asm("tanh.approx.f32 %0, %1;" : "=f"(r) : "f"(x)); return r;
}

#define L2E 1.4426950408889634f

// gate sigmoid via HW tanh: sig(x) = 0.5*tanh(0.5x) + 0.5
__device__ __forceinline__ float fsig_hw(float x) {
    return fmaf(0.5f, tanhf_hw(0.5f * x), 0.5f);
}
__device__ __forceinline__ float ftanh(float x) {   // accurate path (MLP)
    return 2.0f * rcpf(1.0f + ex2f(-2.0f * L2E * x)) - 1.0f;
}

// dummy kernel so ncu (-s 5 -c 1) lands on the GRU kernel
__global__ void nop_kernel() {}

// One persistent block per (batch, direction). 256 threads.
// Thread t: unit i = t & 127, k-half = t >> 7.
//   half 0 (warps 0-3): updaters — combine partials, gates, h update.
//   half 1 (warps 4-7): partials + next-step xw.
// Barrier protocol (no full __syncthreads in the step loop):
//   bar1 (256): h1 arrive after part STS; upd sync before phase 2.
//   bar3 (256): upd arrive after h STS;  h1 sync before next dot.
//   bar2 (128): upd-only sync — orders h writes among updaters.
//   bar4 (128): h1-only sync — yu_s chunk staging.
__global__ void __launch_bounds__(256, 1) gru_persist_kernel(
    const float* __restrict__ y, const float* __restrict__ u,
    const float* __restrict__ Wi_f, const float* __restrict__ bi_f,
    const float* __restrict__ Wh_f, const float* __restrict__ bhn_f,
    const float* __restrict__ Wi_b, const float* __restrict__ bi_b,
    const float* __restrict__ Wh_b, const float* __restrict__ bhn_b)
{
    const int blk  = blockIdx.x;        // 0..127
    const int b    = blk & (BATCH - 1);
    const int dir  = blk >> 6;          // 0 = fwd, 1 = bwd
    const int t    = threadIdx.x;       // 0..255
    const int i    = t & (H - 1);       // unit 0..127
    const int half = t >> 7;            // k-half
    const int k0   = half * HALF;
    const bool upd = (t < H);           // warps 0-3

    const float* Wi  = dir ? Wi_b  : Wi_f;
    const float* bi  = dir ? bi_b  : bi_f;
    const float* Wh  = dir ? Wh_b  : Wh_f;
    const float* bhn = dir ? bhn_b : bhn_f;

    // ---- register-resident recurrent weights: 3 gates x half-k, packed ----
    ull_t wr[HALF / 2], wz[HALF / 2], wn[HALF / 2];
#pragma unroll
    for (int m = 0; m < HALF / 2; ++m) {
        const float* r0 = Wh + (size_t)(k0 + 2 * m)     * H3;
        const float* r1 = Wh + (size_t)(k0 + 2 * m + 1) * H3;
        wr[m] = pack2(r0[i],         r1[i]);
        wz[m] = pack2(r0[i + H],     r1[i + H]);
        wn[m] = pack2(r0[i + 2 * H], r1[i + 2 * H]);
    }

    // ---- shared state ----
    __shared__ __align__(16) float  h_s[H];
    __shared__ __align__(16) float4 part_s[H];        // (pr,pz,pn,-) from half 1
    __shared__ __align__(16) float4 xw_s[2][H];       // ping-pong (xwr,xwz,xwn,-)
    __shared__ __align__(16) float4 yu_s[TILE * 2];   // per step: y(4)+u(4)
    __shared__ __align__(16) float4 wi4_s[2 * H3];    // Wi columns, 2 float4 each

    for (int col = t; col < H3; col += 256) {
        wi4_s[col]      = make_float4(Wi[0 * H3 + col], Wi[1 * H3 + col],
                                      Wi[2 * H3 + col], Wi[3 * H3 + col]);
        wi4_s[H3 + col] = make_float4(Wi[4 * H3 + col], Wi[5 * H3 + col],
                                      Wi[6 * H3 + col], Wi[7 * H3 + col]);
    }

    float bhn_i = 0.0f, bir = 0.0f, biz = 0.0f, bin = 0.0f;
    if (upd) {
        bhn_i = bhn[i];
    } else {
        bir = bi[i]; biz = bi[i + H]; bin = bi[i + 2 * H];
    }

    if (t < H) h_s[t] = 0.0f;
    __syncthreads();

    float hsum = 0.0f;                  // updaters only

    const int nchunk = TT / TILE;
    for (int c = 0; c < nchunk; ++c) {
        const int t0 = dir ? (TT - (c + 1) * TILE) : (c * TILE);
        const int tt0 = dir ? (TILE - 1) : 0;
        const int sgn = dir ? -1 : 1;

        if (!upd) {                     // half-1 stages inputs + step-0 xw
            const int tc = t0 + i;
            yu_s[2 * i]     = *(const float4*)(y + ((size_t)b * TT + tc) * 4);
            yu_s[2 * i + 1] = *(const float4*)(u + ((size_t)b * TT + tc) * 4);
            asm volatile("bar.sync 4, 128;" ::: "memory");   // h1-only

            const float4 ya = yu_s[2 * tt0];
            const float4 ub = yu_s[2 * tt0 + 1];
            const float4 war = wi4_s[i],          wbr = wi4_s[H3 + i];
            const float4 waz = wi4_s[i + H],      wbz = wi4_s[H3 + i + H];
            const float4 wan = wi4_s[i + 2 * H],  wbn = wi4_s[H3 + i + 2 * H];
            float xr = bir, xz = biz, xn = bin;
            xr = fmaf(ya.x, war.x, xr); xr = fmaf(ya.y, war.y, xr);
            xr = fmaf(ya.z, war.z, xr); xr = fmaf(ya.w, war.w, xr);
            xr = fmaf(ub.x, wbr.x, xr); xr = fmaf(ub.y, wbr.y, xr);
            xr = fmaf(ub.z, wbr.z, xr); xr = fmaf(ub.w, wbr.w, xr);
            xz = fmaf(ya.x, waz.x, xz); xz = fmaf(ya.y, waz.y, xz);
            xz = fmaf(ya.z, waz.z, xz); xz = fmaf(ya.w, waz.w, xz);
            xz = fmaf(ub.x, wbz.x, xz); xz = fmaf(ub.y, wbz.y, xz);
            xz = fmaf(ub.z, wbz.z, xz); xz = fmaf(ub.w, wbz.w, xz);
            xn = fmaf(ya.x, wan.x, xn); xn = fmaf(ya.y, wan.y, xn);
            xn = fmaf(ya.z, wan.z, xn); xn = fmaf(ya.w, wan.w, xn);
            xn = fmaf(ub.x, wbn.x, xn); xn = fmaf(ub.y, wbn.y, xn);
            xn = fmaf(ub.z, wbn.z, xn); xn = fmaf(ub.w, wbn.w, xn);
            xw_s[0][i] = make_float4(xr, xz, xn, 0.0f);
        }

        for (int s = 0; s < TILE; ++s) {
            // ---- phase 1: 3 partial dots over h[k0:k0+64] (all threads) ----
            const ulonglong2* h2 = (const ulonglong2*)(h_s + k0);
            ull_t ar = 0ull, az = 0ull, an = 0ull;
#pragma unroll
            for (int m = 0; m < HALF / 4; ++m) {
                const ulonglong2 hv = h2[m];   // broadcast; shared 3 ways
                ar = ffma2(hv.x, wr[2 * m],     ar);
                az = ffma2(hv.x, wz[2 * m],     az);
                an = ffma2(hv.x, wn[2 * m],     an);
                ar = ffma2(hv.y, wr[2 * m + 1], ar);
                az = ffma2(hv.y, wz[2 * m + 1], az);
                an = ffma2(hv.y, wn[2 * m + 1], an);
            }
            const float pr = lo2(ar) + hi2(ar);
            const float pz = lo2(az) + hi2(az);
            const float pn = lo2(an) + hi2(an);

            if (upd) {
                const float hold = h_s[i];               // pre-bar issue
                asm volatile("bar.sync 1, 256;" ::: "memory");  // part_s ready
                // ---- phase 2: combine + gates + h update (all HW tanh) ----
                const float4 p   = part_s[i];
                const float4 xwv = xw_s[s & 1][i];
                const float r = fsig_hw((xwv.x + pr) + p.x);
                const float z = fsig_hw((xwv.y + pz) + p.y);
                const float pn_full = (pn + p.z) + bhn_i;
                const float arg = fmaf(r, pn_full, xwv.z);
                const float n   = tanhf_hw(arg);
                const float hn  = fmaf(z, hold - n, n);  // (1-z)n + z h
                hsum += hn;
                h_s[i] = hn;
                asm volatile("bar.arrive 3, 256;" ::: "memory"); // h published
                asm volatile("bar.sync 2, 128;"   ::: "memory"); // upd-internal
            } else {
                part_s[i] = make_float4(pr, pz, pn, 0.0f);
                asm volatile("bar.arrive 1, 256;" ::: "memory"); // release upd
                // next step's xw: overlaps updaters' phase 2
                if (s + 1 < TILE) {
                    const int tt_n = tt0 + sgn * (s + 1);
                    const float4 ya = yu_s[2 * tt_n];
                    const float4 ub = yu_s[2 * tt_n + 1];
                    const float4 war = wi4_s[i],         wbr = wi4_s[H3 + i];
                    const float4 waz = wi4_s[i + H],     wbz = wi4_s[H3 + i + H];
                    const float4 wan = wi4_s[i + 2 * H], wbn = wi4_s[H3 + i + 2 * H];
                    float xr = bir, xz = biz, xn = bin;
                    xr = fmaf(ya.x, war.x, xr); xr = fmaf(ya.y, war.y, xr);
                    xr = fmaf(ya.z, war.z, xr); xr = fmaf(ya.w, war.w, xr);
                    xr = fmaf(ub.x, wbr.x, xr); xr = fmaf(ub.y, wbr.y, xr);
                    xr = fmaf(ub.z, wbr.z, xr); xr = fmaf(ub.w, wbr.w, xr);
                    xz = fmaf(ya.x, waz.x, xz); xz = fmaf(ya.y, waz.y, xz);
                    xz = fmaf(ya.z, waz.z, xz); xz = fmaf(ya.w, waz.w, xz);
                    xz = fmaf(ub.x, wbz.x, xz); xz = fmaf(ub.y, wbz.y, xz);
                    xz = fmaf(ub.z, wbz.z, xz); xz = fmaf(ub.w, wbz.w, xz);
                    xn = fmaf(ya.x, wan.x, xn); xn = fmaf(ya.y, wan.y, xn);
                    xn = fmaf(ya.z, wan.z, xn); xn = fmaf(ya.w, wan.w, xn);
                    xn = fmaf(ub.x, wbn.x, xn); xn = fmaf(ub.y, wbn.y, xn);
                    xn = fmaf(ub.z, wbn.z, xn); xn = fmaf(ub.w, wbn.w, xn);
                    xw_s[(s + 1) & 1][i] = make_float4(xr, xz, xn, 0.0f);
                }
                asm volatile("bar.sync 3, 256;" ::: "memory");   // wait for h
            }
        }
    }

    if (upd)
        g_feat[b * (2 * H) + dir * H + i] = hsum * (1.0f / (float)TT);
}

// MLP heads: 256 -> 128 -> 64 -> 20, tanh, tanh, linear. (accurate tanh)
__global__ void __launch_bounds__(128) mlp_kernel(
    const float* __restrict__ mW0, const float* __restrict__ mb0,
    const float* __restrict__ mW1, const float* __restrict__ mb1,
    const float* __restrict__ mW2, const float* __restrict__ mb2,
    const float* __restrict__ sW0, const float* __restrict__ sb0,
    const float* __restrict__ sW1, const float* __restrict__ sb1,
    const float* __restrict__ sW2, const float* __restrict__ sb2,
    float* __restrict__ out)
{
    const int b    = blockIdx.x & (BATCH - 1);
    const int head = blockIdx.x >> 6;
    const int j    = threadIdx.x;

    const float* W0 = head ? sW0 : mW0;
    const float* b0 = head ? sb0 : mb0;
    const float* W1 = head ? sW1 : mW1;
    const float* b1 = head ? sb1 : mb1;
    const float* W2 = head ? sW2 : mW2;
    const float* b2 = head ? sb2 : mb2;

    __shared__ float feat_s[256];
    __shared__ float h1_s[128];
    __shared__ float h2_s[64];

    feat_s[j]       = g_feat[b * 256 + j];
    feat_s[j + 128] = g_feat[b * 256 + j + 128];
    __syncthreads();

    {   // layer 0: 256 -> 128
        float acc = b0[j];
#pragma unroll 8
        for (int i = 0; i < 256; ++i)
            acc = fmaf(feat_s[i], __ldg(W0 + (size_t)i * 128 + j), acc);
        h1_s[j] = ftanh(acc);
    }
    __syncthreads();

    if (j < 64) {   // layer 1: 128 -> 64
        float acc = b1[j];
#pragma unroll 8
        for (int i = 0; i < 128; ++i)
            acc = fmaf(h1_s[i], __ldg(W1 + (size_t)i * 64 + j), acc);
        h2_s[j] = ftanh(acc);
    }
    __syncthreads();

    if (j < 20) {   // layer 2: 64 -> 20
        float acc = b2[j];
#pragma unroll
        for (int i = 0; i < 64; ++i)
            acc = fmaf(h2_s[i], __ldg(W2 + (size_t)i * 20 + j), acc);
        out[head * (BATCH * 20) + b * 20 + j] = acc;
    }
}

extern "C" void kernel_launch(void* const* d_in, const int* in_sizes, int n_in,
                              void* d_out, int out_size)
{
    const float* y     = (const float*)d_in[0];
    const float* u     = (const float*)d_in[1];
    const float* Wi_f  = (const float*)d_in[2];
    const float* bi_f  = (const float*)d_in[3];
    const float* Wh_f  = (const float*)d_in[4];
    const float* bhn_f = (const float*)d_in[5];
    const float* Wi_b  = (const float*)d_in[6];
    const float* bi_b  = (const float*)d_in[7];
    const float* Wh_b  = (const float*)d_in[8];
    const float* bhn_b = (const float*)d_in[9];
    const float* mW0   = (const float*)d_in[10];
    const float* mb0   = (const float*)d_in[11];
    const float* mW1   = (const float*)d_in[12];
    const float* mb1   = (const float*)d_in[13];
    const float* mW2   = (const float*)d_in[14];
    const float* mb2   = (const float*)d_in[15];
    const float* sW0   = (const float*)d_in[16];
    const float* sb0   = (const float*)d_in[17];
    const float* sW1   = (const float*)d_in[18];
    const float* sb1   = (const float*)d_in[19];
    const float* sW2   = (const float*)d_in[20];
    const float* sb2   = (const float*)d_in[21];

    nop_kernel<<<1, 32>>>();
    gru_persist_kernel<<<BATCH * 2, 256>>>(y, u, Wi_f, bi_f, Wh_f, bhn_f,
                                           Wi_b, bi_b, Wh_b, bhn_b);
    nop_kernel<<<1, 32>>>();
    mlp_kernel<<<BATCH * 2, 128>>>(mW0, mb0, mW1, mb1, mW2, mb2,
                                   sW0, sb0, sW1, sb1, sW2, sb2,
                                   (float*)d_out);
}